// round 11
// baseline (speedup 1.0000x reference)
#include <cuda_runtime.h>
#include <cuda_bf16.h>
#include <math.h>
#include <stdint.h>

#define B_SZ   16384
#define D_IN   512
#define HID    512
#define K_DIM  1024
#define N_DIM  2048
#define EPS    1e-5f

// ---------------- device scratch ----------------
__device__ float          g_z[(size_t)B_SZ * N_DIM];          // 128 MB
__device__ __nv_bfloat16  g_Ahi[(size_t)B_SZ * K_DIM];        // 32 MB
__device__ __nv_bfloat16  g_Alo[(size_t)B_SZ * K_DIM];        // 32 MB
__device__ __nv_bfloat16  g_Bhi[(size_t)N_DIM * K_DIM];       // 4 MB  [N,K]
__device__ __nv_bfloat16  g_Blo[(size_t)N_DIM * K_DIM];       // 4 MB

// ---------------- helpers (base sm_103 features only) ----------------------
__device__ __forceinline__ uint32_t smem_u32(const void* p) {
    uint32_t a;
    asm("{ .reg .u64 t; cvta.to.shared.u64 t, %1; cvt.u32.u64 %0, t; }" : "=r"(a) : "l"(p));
    return a;
}
__device__ __forceinline__ void cp_async16(uint32_t dst, const void* src) {
    asm volatile("cp.async.cg.shared.global [%0], [%1], 16;" :: "r"(dst), "l"(src) : "memory");
}
#define CP_COMMIT()  asm volatile("cp.async.commit_group;" ::: "memory")
#define CP_WAIT(n)   asm volatile("cp.async.wait_group %0;" :: "n"(n) : "memory")

__device__ __forceinline__ void ldsm_x4(uint32_t (&r)[4], uint32_t addr) {
    asm volatile("ldmatrix.sync.aligned.m8n8.x4.shared.b16 {%0,%1,%2,%3}, [%4];"
        : "=r"(r[0]), "=r"(r[1]), "=r"(r[2]), "=r"(r[3]) : "r"(addr));
}
__device__ __forceinline__ void mma_bf16(float (&d)[4], const uint32_t (&a)[4],
                                         const uint32_t* b) {
    asm volatile(
        "mma.sync.aligned.m16n8k16.row.col.f32.bf16.bf16.f32 "
        "{%0,%1,%2,%3}, {%4,%5,%6,%7}, {%8,%9}, {%0,%1,%2,%3};"
        : "+f"(d[0]), "+f"(d[1]), "+f"(d[2]), "+f"(d[3])
        : "r"(a[0]), "r"(a[1]), "r"(a[2]), "r"(a[3]), "r"(b[0]), "r"(b[1]));
}

// ---------------------------------------------------------------------------
// convA: cat(x,h) fp32 -> bf16 hi/lo, [B_SZ, K_DIM] K-major
// ---------------------------------------------------------------------------
__global__ __launch_bounds__(256) void convA_kernel(
    const float* __restrict__ x, const float* __restrict__ h)
{
    int gid = blockIdx.x * 256 + threadIdx.x;
    int m   = gid >> 8;
    int c4  = (gid & 255) * 4;
    float4 v = (c4 < D_IN)
        ? *reinterpret_cast<const float4*>(x + (size_t)m * D_IN + c4)
        : *reinterpret_cast<const float4*>(h + (size_t)m * HID + (c4 - D_IN));
    float f[4] = {v.x, v.y, v.z, v.w};
    __nv_bfloat16 hi[4], lo[4];
#pragma unroll
    for (int i = 0; i < 4; i++) {
        hi[i] = __float2bfloat16_rn(f[i]);
        lo[i] = __float2bfloat16_rn(f[i] - __bfloat162float(hi[i]));
    }
    size_t o = (size_t)m * K_DIM + c4;
    *reinterpret_cast<uint2*>(&g_Ahi[o]) = *reinterpret_cast<uint2*>(hi);
    *reinterpret_cast<uint2*>(&g_Alo[o]) = *reinterpret_cast<uint2*>(lo);
}

// ---------------------------------------------------------------------------
// convW: W[K,N] fp32 -> Wt hi/lo [N,K] bf16 (transposed, K-major)
// ---------------------------------------------------------------------------
__global__ __launch_bounds__(1024) void convW_kernel(const float* __restrict__ W)
{
    __shared__ float tile[32][33];
    int tx = threadIdx.x, ty = threadIdx.y;
    int n0 = blockIdx.x * 32, k0 = blockIdx.y * 32;
    tile[ty][tx] = W[(size_t)(k0 + ty) * N_DIM + n0 + tx];
    __syncthreads();
    float v = tile[tx][ty];
    __nv_bfloat16 hi = __float2bfloat16_rn(v);
    __nv_bfloat16 lo = __float2bfloat16_rn(v - __bfloat162float(hi));
    size_t o = (size_t)(n0 + ty) * K_DIM + k0 + tx;
    g_Bhi[o] = hi;
    g_Blo[o] = lo;
}

// ---------------------------------------------------------------------------
// HMMA GEMM: z[128x256 tile] = Ahi@Bhi^T + Ahi@Blo^T + Alo@Bhi^T + bias
// 8 warps (2x4), warp tile 64x64, K-chunk 32, 3-stage cp.async ring.
// stage: Ahi(128) | Alo(128) | Bhi(256) | Blo(256) rows x 32 bf16, stride 80B
// ---------------------------------------------------------------------------
#define KC        32
#define NCHUNK    (K_DIM / KC)            // 32
#define ROW_B     80
#define OFF_ALO   (128 * ROW_B)           // 10240
#define OFF_BHI   (256 * ROW_B)           // 20480
#define OFF_BLO   (OFF_BHI + 256 * ROW_B) // 40960
#define STG_SZ    (OFF_BLO + 256 * ROW_B) // 61440
#define CTRL_SZ   1024
#define NSTAGE    3
#define SMEM_TOTAL (CTRL_SZ + NSTAGE * STG_SZ)   // 185344

__global__ __launch_bounds__(256, 1) void gemm_tc_kernel(const float* __restrict__ bias)
{
    extern __shared__ char smem[];
    const uint32_t sb = smem_u32(smem);
    const int tid  = threadIdx.x;
    const int wid  = tid >> 5;
    const int lane = tid & 31;
    const int wm   = wid >> 2;            // 0..1  (64-row slab)
    const int wn   = wid & 3;             // 0..3  (64-col slab)
    const int n0 = blockIdx.x * 256;
    const int m0 = blockIdx.y * 128;

    float* sbias = reinterpret_cast<float*>(smem);
    if (tid < 256) sbias[tid] = bias[n0 + tid];

    // ---- stage loader: 3072 x 16B cp.async, 12 per thread
    auto load_stage = [&](int s, int kc) {
        const uint32_t stg = sb + CTRL_SZ + s * STG_SZ;
        const int k0 = kc * KC;
#pragma unroll
        for (int it = 0; it < 12; it++) {
            int e = it * 256 + tid;                  // 0..3071
            uint32_t dst;
            const __nv_bfloat16* src;
            if (e < 1024) {                          // A: 512 hi + 512 lo
                int half = e >> 9;
                int idx  = e & 511;
                int r = idx >> 2, j = idx & 3;
                src = (half ? g_Alo : g_Ahi) + (size_t)(m0 + r) * K_DIM + k0 + j * 8;
                dst = stg + (half ? OFF_ALO : 0) + r * ROW_B + j * 16;
            } else {                                 // B: 1024 hi + 1024 lo
                int idx  = e - 1024;
                int half = idx >> 10;
                idx &= 1023;
                int r = idx >> 2, j = idx & 3;
                src = (half ? g_Blo : g_Bhi) + (size_t)(n0 + r) * K_DIM + k0 + j * 8;
                dst = stg + (half ? OFF_BLO : OFF_BHI) + r * ROW_B + j * 16;
            }
            cp_async16(dst, src);
        }
        CP_COMMIT();
    };

    float acc[4][8][4];
#pragma unroll
    for (int mt = 0; mt < 4; mt++)
#pragma unroll
        for (int nt = 0; nt < 8; nt++)
#pragma unroll
            for (int e = 0; e < 4; e++) acc[mt][nt][e] = 0.0f;

    // ldmatrix lane-address components (validated in R7)
    const int a_row_in = lane & 15;
    const int a_kh     = lane >> 4;
    const int b_oct    = lane >> 4;
    const int b_kh     = (lane >> 3) & 1;
    const int b_rin    = lane & 7;

    load_stage(0, 0);
    load_stage(1, 1);

    for (int c = 0; c < NCHUNK; c++) {
        if (c + 2 < NCHUNK) { CP_WAIT(1); } else { CP_WAIT(0); }
        __syncthreads();
        if (c + 2 < NCHUNK) load_stage((c + 2) % NSTAGE, c + 2);

        const uint32_t stg = sb + CTRL_SZ + (c % NSTAGE) * STG_SZ;
        const uint32_t aBase = stg + (wm * 64 + a_row_in) * ROW_B + a_kh * 16;
        const uint32_t bBase = stg + OFF_BHI
                             + (wn * 64 + b_oct * 8 + b_rin) * ROW_B + b_kh * 16;

#pragma unroll
        for (int ks = 0; ks < 2; ks++) {          // two k16 slices per chunk
            uint32_t ahi[4][4], alo[4][4];
#pragma unroll
            for (int mt = 0; mt < 4; mt++) {
                uint32_t ad = aBase + mt * (16 * ROW_B) + ks * 32;
                ldsm_x4(ahi[mt], ad);
                ldsm_x4(alo[mt], ad + OFF_ALO);
            }
#pragma unroll
            for (int bt = 0; bt < 4; bt++) {
                uint32_t bh[4], bl[4];
                uint32_t bd = bBase + bt * (16 * ROW_B) + ks * 32;
                ldsm_x4(bh, bd);
                ldsm_x4(bl, bd + (OFF_BLO - OFF_BHI));
#pragma unroll
                for (int mt = 0; mt < 4; mt++)
#pragma unroll
                    for (int half = 0; half < 2; half++) {
                        float (&d)[4] = acc[mt][bt * 2 + half];
                        mma_bf16(d, ahi[mt], &bh[half * 2]);
                        mma_bf16(d, ahi[mt], &bl[half * 2]);
                        mma_bf16(d, alo[mt], &bh[half * 2]);
                    }
            }
        }
    }

    // ---- epilogue: acc -> g_z (+bias)
    const int g   = lane >> 2;
    const int tig = lane & 3;
#pragma unroll
    for (int mt = 0; mt < 4; mt++) {
        int row0 = m0 + wm * 64 + mt * 16 + g;
#pragma unroll
        for (int nt = 0; nt < 8; nt++) {
            int ncol = wn * 64 + nt * 8 + tig * 2;
            float b0 = sbias[ncol], b1 = sbias[ncol + 1];
            float2 v0 = make_float2(acc[mt][nt][0] + b0, acc[mt][nt][1] + b1);
            float2 v1 = make_float2(acc[mt][nt][2] + b0, acc[mt][nt][3] + b1);
            *reinterpret_cast<float2*>(g_z + (size_t)row0 * N_DIM + n0 + ncol) = v0;
            *reinterpret_cast<float2*>(g_z + (size_t)(row0 + 8) * N_DIM + n0 + ncol) = v1;
        }
    }
}

// ---------------------------------------------------------------------------
// fused GroupNorm(4) + FiLM + LSTM + GroupNorm(1) (validated; ~115us)
// ---------------------------------------------------------------------------
__device__ __forceinline__ float sigmoidf_(float v) {
    return 1.0f / (1.0f + expf(-v));
}

__global__ __launch_bounds__(512) void fused_kernel(
    const float* __restrict__ c, const float* __restrict__ u,
    const float* __restrict__ gamma, const float* __restrict__ beta,
    float* __restrict__ out)
{
    const int row  = blockIdx.x;
    const int t    = threadIdx.x;
    const int warp = t >> 5;
    const int lane = t & 31;

    const float* zr = g_z + (size_t)row * N_DIM;
    float z[4];
    z[0] = zr[t];
    z[1] = zr[t + 512];
    z[2] = zr[t + 1024];
    z[3] = zr[t + 1536];

    __shared__ float sred[16][8];
    __shared__ float sfin[8];

    float p[8];
#pragma unroll
    for (int q = 0; q < 4; q++) { p[q] = z[q]; p[4 + q] = z[q] * z[q]; }
#pragma unroll
    for (int off = 16; off > 0; off >>= 1)
#pragma unroll
        for (int q = 0; q < 8; q++)
            p[q] += __shfl_down_sync(0xFFFFFFFFu, p[q], off);
    if (lane == 0)
#pragma unroll
        for (int q = 0; q < 8; q++) sred[warp][q] = p[q];
    __syncthreads();
    if (t < 8) {
        float s = 0.0f;
#pragma unroll
        for (int w = 0; w < 16; w++) s += sred[w][t];
        sfin[t] = s;
    }
    __syncthreads();

    float mean[4], rstd[4];
#pragma unroll
    for (int g = 0; g < 4; g++) {
        mean[g] = sfin[g] * (1.0f / 512.0f);
        float var = sfin[4 + g] * (1.0f / 512.0f) - mean[g] * mean[g];
        rstd[g] = rsqrtf(var + EPS);
    }

    const float* ur = u + (size_t)row * (2 * N_DIM);
    float zn[4];
#pragma unroll
    for (int g = 0; g < 4; g++) {
        int idx = g * 512 + t;
        float a  = ur[idx];
        float bb = ur[N_DIM + idx];
        zn[g] = (z[g] - mean[g]) * rstd[g] * (1.0f + a) + bb;
    }

    float cv    = c[(size_t)row * HID + t];
    float c_new = sigmoidf_(zn[1]) * cv + sigmoidf_(zn[0]) * tanhf(zn[3]);

    float s = c_new, ss = c_new * c_new;
#pragma unroll
    for (int off = 16; off > 0; off >>= 1) {
        s  += __shfl_down_sync(0xFFFFFFFFu, s, off);
        ss += __shfl_down_sync(0xFFFFFFFFu, ss, off);
    }
    if (lane == 0) { sred[warp][0] = s; sred[warp][1] = ss; }
    __syncthreads();
    if (t < 2) {
        float acc = 0.0f;
#pragma unroll
        for (int w = 0; w < 16; w++) acc += sred[w][t];
        sfin[t] = acc;
    }
    __syncthreads();

    float m2 = sfin[0] * (1.0f / 512.0f);
    float v2 = sfin[1] * (1.0f / 512.0f) - m2 * m2;
    float cn = (c_new - m2) * rsqrtf(v2 + EPS) * gamma[t] + beta[t];

    float h_new = sigmoidf_(zn[2]) * tanhf(cn);

    out[(size_t)row * HID + t] = h_new;
    out[(size_t)B_SZ * HID + (size_t)row * HID + t] = c_new;
}

// ---------------------------------------------------------------------------
extern "C" void kernel_launch(void* const* d_in, const int* in_sizes, int n_in,
                              void* d_out, int out_size)
{
    const float* x     = (const float*)d_in[0];
    const float* h     = (const float*)d_in[1];
    const float* c     = (const float*)d_in[2];
    const float* u     = (const float*)d_in[3];
    const float* W     = (const float*)d_in[4];
    const float* b_lin = (const float*)d_in[5];
    const float* gamma = (const float*)d_in[6];
    const float* beta  = (const float*)d_in[7];
    float* out = (float*)d_out;

    cudaFuncSetAttribute(gemm_tc_kernel,
                         cudaFuncAttributeMaxDynamicSharedMemorySize, SMEM_TOTAL);

    convA_kernel<<<(B_SZ * K_DIM / 4) / 256, 256>>>(x, h);
    convW_kernel<<<dim3(N_DIM / 32, K_DIM / 32), dim3(32, 32)>>>(W);
    gemm_tc_kernel<<<dim3(N_DIM / 256, B_SZ / 128), 256, SMEM_TOTAL>>>(b_lin);
    fused_kernel<<<B_SZ, 512>>>(c, u, gamma, beta, out);
}

// round 13
// speedup vs baseline: 1.7862x; 1.7862x over previous
#include <cuda_runtime.h>
#include <cuda_fp16.h>
#include <math.h>
#include <stdint.h>

#define B_SZ   16384
#define D_IN   512
#define HID    512
#define K_DIM  1024
#define N_DIM  2048
#define EPS    1e-5f

// ---------------- device scratch ----------------
__device__ float   g_z[(size_t)B_SZ * N_DIM];          // 128 MB
__device__ __half  g_A[(size_t)B_SZ * K_DIM];          // 32 MB  [M,K]
__device__ __half  g_B[(size_t)N_DIM * K_DIM];         // 4 MB   [N,K]

// ---------------- helpers (base sm_103 features only) ----------------------
__device__ __forceinline__ uint32_t smem_u32(const void* p) {
    uint32_t a;
    asm("{ .reg .u64 t; cvta.to.shared.u64 t, %1; cvt.u32.u64 %0, t; }" : "=r"(a) : "l"(p));
    return a;
}
__device__ __forceinline__ void cp_async16(uint32_t dst, const void* src) {
    asm volatile("cp.async.cg.shared.global [%0], [%1], 16;" :: "r"(dst), "l"(src) : "memory");
}
#define CP_COMMIT()  asm volatile("cp.async.commit_group;" ::: "memory")
#define CP_WAIT(n)   asm volatile("cp.async.wait_group %0;" :: "n"(n) : "memory")

__device__ __forceinline__ void ldsm_x4(uint32_t (&r)[4], uint32_t addr) {
    asm volatile("ldmatrix.sync.aligned.m8n8.x4.shared.b16 {%0,%1,%2,%3}, [%4];"
        : "=r"(r[0]), "=r"(r[1]), "=r"(r[2]), "=r"(r[3]) : "r"(addr));
}
__device__ __forceinline__ void mma_f16(float (&d)[4], const uint32_t (&a)[4],
                                        const uint32_t* b) {
    asm volatile(
        "mma.sync.aligned.m16n8k16.row.col.f32.f16.f16.f32 "
        "{%0,%1,%2,%3}, {%4,%5,%6,%7}, {%8,%9}, {%0,%1,%2,%3};"
        : "+f"(d[0]), "+f"(d[1]), "+f"(d[2]), "+f"(d[3])
        : "r"(a[0]), "r"(a[1]), "r"(a[2]), "r"(a[3]), "r"(b[0]), "r"(b[1]));
}

// ---------------------------------------------------------------------------
// convA: cat(x,h) fp32 -> fp16, [B_SZ, K_DIM] K-major
// ---------------------------------------------------------------------------
__global__ __launch_bounds__(256) void convA_kernel(
    const float* __restrict__ x, const float* __restrict__ h)
{
    int gid = blockIdx.x * 256 + threadIdx.x;
    int m   = gid >> 8;
    int c4  = (gid & 255) * 4;
    float4 v = (c4 < D_IN)
        ? *reinterpret_cast<const float4*>(x + (size_t)m * D_IN + c4)
        : *reinterpret_cast<const float4*>(h + (size_t)m * HID + (c4 - D_IN));
    __half q[4];
    q[0] = __float2half_rn(v.x);
    q[1] = __float2half_rn(v.y);
    q[2] = __float2half_rn(v.z);
    q[3] = __float2half_rn(v.w);
    *reinterpret_cast<uint2*>(&g_A[(size_t)m * K_DIM + c4]) =
        *reinterpret_cast<uint2*>(q);
}

// ---------------------------------------------------------------------------
// convW: W[K,N] fp32 -> Wt fp16 [N,K] (transposed, K-major)
// ---------------------------------------------------------------------------
__global__ __launch_bounds__(1024) void convW_kernel(const float* __restrict__ W)
{
    __shared__ float tile[32][33];
    int tx = threadIdx.x, ty = threadIdx.y;
    int n0 = blockIdx.x * 32, k0 = blockIdx.y * 32;
    tile[ty][tx] = W[(size_t)(k0 + ty) * N_DIM + n0 + tx];
    __syncthreads();
    g_B[(size_t)(n0 + ty) * K_DIM + k0 + tx] = __float2half_rn(tile[tx][ty]);
}

// ---------------------------------------------------------------------------
// HMMA GEMM: z[128x256 tile] = A @ B^T + bias   (single fp16 pass)
// 8 warps (2x4), warp tile 64x64, K-chunk 32, 3-stage cp.async ring.
// stage: A(128 rows) | B(256 rows), each row 32 fp16 (64B), stride 80B.
// ---------------------------------------------------------------------------
#define KC        32
#define NCHUNK    (K_DIM / KC)            // 32
#define ROW_B     80
#define OFF_B     (128 * ROW_B)           // 10240
#define STG_SZ    (OFF_B + 256 * ROW_B)   // 30720
#define CTRL_SZ   1024
#define NSTAGE    3
#define SMEM_TOTAL (CTRL_SZ + NSTAGE * STG_SZ)   // 93184

__global__ __launch_bounds__(256, 1) void gemm_tc_kernel(const float* __restrict__ bias)
{
    extern __shared__ char smem[];
    const uint32_t sb = smem_u32(smem);
    const int tid  = threadIdx.x;
    const int wid  = tid >> 5;
    const int lane = tid & 31;
    const int wm   = wid >> 2;            // 0..1  (64-row slab)
    const int wn   = wid & 3;             // 0..3  (64-col slab)
    const int n0 = blockIdx.x * 256;
    const int m0 = blockIdx.y * 128;

    float* sbias = reinterpret_cast<float*>(smem);
    if (tid < 256) sbias[tid] = bias[n0 + tid];

    // ---- stage loader: 1536 x 16B cp.async, 6 per thread
    auto load_stage = [&](int s, int kc) {
        const uint32_t stg = sb + CTRL_SZ + s * STG_SZ;
        const int k0 = kc * KC;
#pragma unroll
        for (int it = 0; it < 6; it++) {
            int e = it * 256 + tid;                  // 0..1535
            uint32_t dst;
            const __half* src;
            if (e < 512) {                           // A: 128 rows x 4 chunks
                int r = e >> 2, j = e & 3;
                src = g_A + (size_t)(m0 + r) * K_DIM + k0 + j * 8;
                dst = stg + r * ROW_B + j * 16;
            } else {                                 // B: 256 rows x 4 chunks
                int idx = e - 512;
                int r = idx >> 2, j = idx & 3;
                src = g_B + (size_t)(n0 + r) * K_DIM + k0 + j * 8;
                dst = stg + OFF_B + r * ROW_B + j * 16;
            }
            cp_async16(dst, src);
        }
        CP_COMMIT();
    };

    float acc[4][8][4];
#pragma unroll
    for (int mt = 0; mt < 4; mt++)
#pragma unroll
        for (int nt = 0; nt < 8; nt++)
#pragma unroll
            for (int e = 0; e < 4; e++) acc[mt][nt][e] = 0.0f;

    // ldmatrix lane-address components (validated in R7/R11)
    const int a_row_in = lane & 15;
    const int a_kh     = lane >> 4;
    const int b_oct    = lane >> 4;
    const int b_kh     = (lane >> 3) & 1;
    const int b_rin    = lane & 7;

    load_stage(0, 0);
    load_stage(1, 1);

    for (int c = 0; c < NCHUNK; c++) {
        if (c + 2 < NCHUNK) { CP_WAIT(1); } else { CP_WAIT(0); }
        __syncthreads();
        if (c + 2 < NCHUNK) load_stage((c + 2) % NSTAGE, c + 2);

        const uint32_t stg = sb + CTRL_SZ + (c % NSTAGE) * STG_SZ;
        const uint32_t aBase = stg + (wm * 64 + a_row_in) * ROW_B + a_kh * 16;
        const uint32_t bBase = stg + OFF_B
                             + (wn * 64 + b_oct * 8 + b_rin) * ROW_B + b_kh * 16;

#pragma unroll
        for (int ks = 0; ks < 2; ks++) {          // two k16 slices per chunk
            uint32_t af[4][4];
#pragma unroll
            for (int mt = 0; mt < 4; mt++)
                ldsm_x4(af[mt], aBase + mt * (16 * ROW_B) + ks * 32);
#pragma unroll
            for (int bt = 0; bt < 4; bt++) {
                uint32_t bf[4];
                ldsm_x4(bf, bBase + bt * (16 * ROW_B) + ks * 32);
#pragma unroll
                for (int mt = 0; mt < 4; mt++)
#pragma unroll
                    for (int half = 0; half < 2; half++)
                        mma_f16(acc[mt][bt * 2 + half], af[mt], &bf[half * 2]);
            }
        }
    }

    // ---- epilogue: acc -> g_z (+bias)
    const int g   = lane >> 2;
    const int tig = lane & 3;
#pragma unroll
    for (int mt = 0; mt < 4; mt++) {
        int row0 = m0 + wm * 64 + mt * 16 + g;
#pragma unroll
        for (int nt = 0; nt < 8; nt++) {
            int ncol = wn * 64 + nt * 8 + tig * 2;
            float b0 = sbias[ncol], b1 = sbias[ncol + 1];
            float2 v0 = make_float2(acc[mt][nt][0] + b0, acc[mt][nt][1] + b1);
            float2 v1 = make_float2(acc[mt][nt][2] + b0, acc[mt][nt][3] + b1);
            *reinterpret_cast<float2*>(g_z + (size_t)row0 * N_DIM + n0 + ncol) = v0;
            *reinterpret_cast<float2*>(g_z + (size_t)(row0 + 8) * N_DIM + n0 + ncol) = v1;
        }
    }
}

// ---------------------------------------------------------------------------
// fused GroupNorm(4) + FiLM + LSTM + GroupNorm(1) (validated; ~110us)
// ---------------------------------------------------------------------------
__device__ __forceinline__ float sigmoidf_(float v) {
    return 1.0f / (1.0f + expf(-v));
}

__global__ __launch_bounds__(512) void fused_kernel(
    const float* __restrict__ c, const float* __restrict__ u,
    const float* __restrict__ gamma, const float* __restrict__ beta,
    float* __restrict__ out)
{
    const int row  = blockIdx.x;
    const int t    = threadIdx.x;
    const int warp = t >> 5;
    const int lane = t & 31;

    const float* zr = g_z + (size_t)row * N_DIM;
    float z[4];
    z[0] = zr[t];
    z[1] = zr[t + 512];
    z[2] = zr[t + 1024];
    z[3] = zr[t + 1536];

    __shared__ float sred[16][8];
    __shared__ float sfin[8];

    float p[8];
#pragma unroll
    for (int q = 0; q < 4; q++) { p[q] = z[q]; p[4 + q] = z[q] * z[q]; }
#pragma unroll
    for (int off = 16; off > 0; off >>= 1)
#pragma unroll
        for (int q = 0; q < 8; q++)
            p[q] += __shfl_down_sync(0xFFFFFFFFu, p[q], off);
    if (lane == 0)
#pragma unroll
        for (int q = 0; q < 8; q++) sred[warp][q] = p[q];
    __syncthreads();
    if (t < 8) {
        float s = 0.0f;
#pragma unroll
        for (int w = 0; w < 16; w++) s += sred[w][t];
        sfin[t] = s;
    }
    __syncthreads();

    float mean[4], rstd[4];
#pragma unroll
    for (int g = 0; g < 4; g++) {
        mean[g] = sfin[g] * (1.0f / 512.0f);
        float var = sfin[4 + g] * (1.0f / 512.0f) - mean[g] * mean[g];
        rstd[g] = rsqrtf(var + EPS);
    }

    const float* ur = u + (size_t)row * (2 * N_DIM);
    float zn[4];
#pragma unroll
    for (int g = 0; g < 4; g++) {
        int idx = g * 512 + t;
        float a  = ur[idx];
        float bb = ur[N_DIM + idx];
        zn[g] = (z[g] - mean[g]) * rstd[g] * (1.0f + a) + bb;
    }

    float cv    = c[(size_t)row * HID + t];
    float c_new = sigmoidf_(zn[1]) * cv + sigmoidf_(zn[0]) * tanhf(zn[3]);

    float s = c_new, ss = c_new * c_new;
#pragma unroll
    for (int off = 16; off > 0; off >>= 1) {
        s  += __shfl_down_sync(0xFFFFFFFFu, s, off);
        ss += __shfl_down_sync(0xFFFFFFFFu, ss, off);
    }
    if (lane == 0) { sred[warp][0] = s; sred[warp][1] = ss; }
    __syncthreads();
    if (t < 2) {
        float acc = 0.0f;
#pragma unroll
        for (int w = 0; w < 16; w++) acc += sred[w][t];
        sfin[t] = acc;
    }
    __syncthreads();

    float m2 = sfin[0] * (1.0f / 512.0f);
    float v2 = sfin[1] * (1.0f / 512.0f) - m2 * m2;
    float cn = (c_new - m2) * rsqrtf(v2 + EPS) * gamma[t] + beta[t];

    float h_new = sigmoidf_(zn[2]) * tanhf(cn);

    out[(size_t)row * HID + t] = h_new;
    out[(size_t)B_SZ * HID + (size_t)row * HID + t] = c_new;
}

// ---------------------------------------------------------------------------
extern "C" void kernel_launch(void* const* d_in, const int* in_sizes, int n_in,
                              void* d_out, int out_size)
{
    const float* x     = (const float*)d_in[0];
    const float* h     = (const float*)d_in[1];
    const float* c     = (const float*)d_in[2];
    const float* u     = (const float*)d_in[3];
    const float* W     = (const float*)d_in[4];
    const float* b_lin = (const float*)d_in[5];
    const float* gamma = (const float*)d_in[6];
    const float* beta  = (const float*)d_in[7];
    float* out = (float*)d_out;

    cudaFuncSetAttribute(gemm_tc_kernel,
                         cudaFuncAttributeMaxDynamicSharedMemorySize, SMEM_TOTAL);

    convA_kernel<<<(B_SZ * K_DIM / 4) / 256, 256>>>(x, h);
    convW_kernel<<<dim3(N_DIM / 32, K_DIM / 32), dim3(32, 32)>>>(W);
    gemm_tc_kernel<<<dim3(N_DIM / 256, B_SZ / 128), 256, SMEM_TOTAL>>>(b_lin);
    fused_kernel<<<B_SZ, 512>>>(c, u, gamma, beta, out);
}

// round 16
// speedup vs baseline: 1.8021x; 1.0089x over previous
#include <cuda_runtime.h>
#include <cuda_fp16.h>
#include <math.h>
#include <stdint.h>

#define B_SZ   16384
#define D_IN   512
#define HID    512
#define K_DIM  1024
#define N_DIM  2048
#define EPS    1e-5f

// ---------------- device scratch ----------------
__device__ __half  g_z[(size_t)B_SZ * N_DIM];          // 64 MB (fp16 z)
__device__ __half  g_A[(size_t)B_SZ * K_DIM];          // 32 MB  [M,K]
__device__ __half  g_B[(size_t)N_DIM * K_DIM];         // 4 MB   [N,K]

// ---------------- helpers (base sm_103 features only) ----------------------
__device__ __forceinline__ uint32_t smem_u32(const void* p) {
    uint32_t a;
    asm("{ .reg .u64 t; cvta.to.shared.u64 t, %1; cvt.u32.u64 %0, t; }" : "=r"(a) : "l"(p));
    return a;
}
__device__ __forceinline__ void cp_async16(uint32_t dst, const void* src) {
    asm volatile("cp.async.cg.shared.global [%0], [%1], 16;" :: "r"(dst), "l"(src) : "memory");
}
#define CP_COMMIT()  asm volatile("cp.async.commit_group;" ::: "memory")
#define CP_WAIT(n)   asm volatile("cp.async.wait_group %0;" :: "n"(n) : "memory")

__device__ __forceinline__ void ldsm_x4(uint32_t (&r)[4], uint32_t addr) {
    asm volatile("ldmatrix.sync.aligned.m8n8.x4.shared.b16 {%0,%1,%2,%3}, [%4];"
        : "=r"(r[0]), "=r"(r[1]), "=r"(r[2]), "=r"(r[3]) : "r"(addr));
}
__device__ __forceinline__ void mma_f16(float (&d)[4], const uint32_t (&a)[4],
                                        const uint32_t* b) {
    asm volatile(
        "mma.sync.aligned.m16n8k16.row.col.f32.f16.f16.f32 "
        "{%0,%1,%2,%3}, {%4,%5,%6,%7}, {%8,%9}, {%0,%1,%2,%3};"
        : "+f"(d[0]), "+f"(d[1]), "+f"(d[2]), "+f"(d[3])
        : "r"(a[0]), "r"(a[1]), "r"(a[2]), "r"(a[3]), "r"(b[0]), "r"(b[1]));
}

// ---------------------------------------------------------------------------
// convA: cat(x,h) fp32 -> fp16, [B_SZ, K_DIM] K-major
// ---------------------------------------------------------------------------
__global__ __launch_bounds__(256) void convA_kernel(
    const float* __restrict__ x, const float* __restrict__ h)
{
    int gid = blockIdx.x * 256 + threadIdx.x;
    int m   = gid >> 8;
    int c4  = (gid & 255) * 4;
    float4 v = (c4 < D_IN)
        ? *reinterpret_cast<const float4*>(x + (size_t)m * D_IN + c4)
        : *reinterpret_cast<const float4*>(h + (size_t)m * HID + (c4 - D_IN));
    __half q[4];
    q[0] = __float2half_rn(v.x);
    q[1] = __float2half_rn(v.y);
    q[2] = __float2half_rn(v.z);
    q[3] = __float2half_rn(v.w);
    *reinterpret_cast<uint2*>(&g_A[(size_t)m * K_DIM + c4]) =
        *reinterpret_cast<uint2*>(q);
}

// ---------------------------------------------------------------------------
// convW: W[K,N] fp32 -> Wt fp16 [N,K] (transposed, K-major)
// ---------------------------------------------------------------------------
__global__ __launch_bounds__(1024) void convW_kernel(const float* __restrict__ W)
{
    __shared__ float tile[32][33];
    int tx = threadIdx.x, ty = threadIdx.y;
    int n0 = blockIdx.x * 32, k0 = blockIdx.y * 32;
    tile[ty][tx] = W[(size_t)(k0 + ty) * N_DIM + n0 + tx];
    __syncthreads();
    g_B[(size_t)(n0 + ty) * K_DIM + k0 + tx] = __float2half_rn(tile[tx][ty]);
}

// ---------------------------------------------------------------------------
// HMMA GEMM: z[128x256 tile] = A @ B^T + bias   (single fp16 pass)
// 8 warps (2x4), warp tile 64x64, K-chunk 32, 3-stage cp.async ring.
// stage: A(128 rows) | B(256 rows), each row 32 fp16 (64B), stride 80B.
// ---------------------------------------------------------------------------
#define KC        32
#define NCHUNK    (K_DIM / KC)            // 32
#define ROW_B     80
#define OFF_B     (128 * ROW_B)           // 10240
#define STG_SZ    (OFF_B + 256 * ROW_B)   // 30720
#define CTRL_SZ   1024
#define NSTAGE    3
#define SMEM_TOTAL (CTRL_SZ + NSTAGE * STG_SZ)   // 93184

__global__ __launch_bounds__(256, 1) void gemm_tc_kernel(const float* __restrict__ bias)
{
    extern __shared__ char smem[];
    const uint32_t sb = smem_u32(smem);
    const int tid  = threadIdx.x;
    const int wid  = tid >> 5;
    const int lane = tid & 31;
    const int wm   = wid >> 2;            // 0..1  (64-row slab)
    const int wn   = wid & 3;             // 0..3  (64-col slab)
    const int n0 = blockIdx.x * 256;
    const int m0 = blockIdx.y * 128;

    float* sbias = reinterpret_cast<float*>(smem);
    if (tid < 256) sbias[tid] = bias[n0 + tid];

    // ---- stage loader: 1536 x 16B cp.async, 6 per thread
    auto load_stage = [&](int s, int kc) {
        const uint32_t stg = sb + CTRL_SZ + s * STG_SZ;
        const int k0 = kc * KC;
#pragma unroll
        for (int it = 0; it < 6; it++) {
            int e = it * 256 + tid;                  // 0..1535
            uint32_t dst;
            const __half* src;
            if (e < 512) {                           // A: 128 rows x 4 chunks
                int r = e >> 2, j = e & 3;
                src = g_A + (size_t)(m0 + r) * K_DIM + k0 + j * 8;
                dst = stg + r * ROW_B + j * 16;
            } else {                                 // B: 256 rows x 4 chunks
                int idx = e - 512;
                int r = idx >> 2, j = idx & 3;
                src = g_B + (size_t)(n0 + r) * K_DIM + k0 + j * 8;
                dst = stg + OFF_B + r * ROW_B + j * 16;
            }
            cp_async16(dst, src);
        }
        CP_COMMIT();
    };

    float acc[4][8][4];
#pragma unroll
    for (int mt = 0; mt < 4; mt++)
#pragma unroll
        for (int nt = 0; nt < 8; nt++)
#pragma unroll
            for (int e = 0; e < 4; e++) acc[mt][nt][e] = 0.0f;

    // ldmatrix lane-address components (validated in R7/R11/R13)
    const int a_row_in = lane & 15;
    const int a_kh     = lane >> 4;
    const int b_oct    = lane >> 4;
    const int b_kh     = (lane >> 3) & 1;
    const int b_rin    = lane & 7;

    load_stage(0, 0);
    load_stage(1, 1);

    for (int c = 0; c < NCHUNK; c++) {
        if (c + 2 < NCHUNK) { CP_WAIT(1); } else { CP_WAIT(0); }
        __syncthreads();
        if (c + 2 < NCHUNK) load_stage((c + 2) % NSTAGE, c + 2);

        const uint32_t stg = sb + CTRL_SZ + (c % NSTAGE) * STG_SZ;
        const uint32_t aBase = stg + (wm * 64 + a_row_in) * ROW_B + a_kh * 16;
        const uint32_t bBase = stg + OFF_B
                             + (wn * 64 + b_oct * 8 + b_rin) * ROW_B + b_kh * 16;

#pragma unroll
        for (int ks = 0; ks < 2; ks++) {          // two k16 slices per chunk
            uint32_t af[4][4];
#pragma unroll
            for (int mt = 0; mt < 4; mt++)
                ldsm_x4(af[mt], aBase + mt * (16 * ROW_B) + ks * 32);
#pragma unroll
            for (int bt = 0; bt < 4; bt++) {
                uint32_t bf[4];
                ldsm_x4(bf, bBase + bt * (16 * ROW_B) + ks * 32);
#pragma unroll
                for (int mt = 0; mt < 4; mt++)
#pragma unroll
                    for (int half = 0; half < 2; half++)
                        mma_f16(acc[mt][bt * 2 + half], af[mt], &bf[half * 2]);
            }
        }
    }

    // ---- epilogue: acc (+bias) -> g_z as fp16
    const int g   = lane >> 2;
    const int tig = lane & 3;
#pragma unroll
    for (int mt = 0; mt < 4; mt++) {
        int row0 = m0 + wm * 64 + mt * 16 + g;
#pragma unroll
        for (int nt = 0; nt < 8; nt++) {
            int ncol = wn * 64 + nt * 8 + tig * 2;
            float b0 = sbias[ncol], b1 = sbias[ncol + 1];
            __half2 v0 = __floats2half2_rn(acc[mt][nt][0] + b0, acc[mt][nt][1] + b1);
            __half2 v1 = __floats2half2_rn(acc[mt][nt][2] + b0, acc[mt][nt][3] + b1);
            *reinterpret_cast<__half2*>(g_z + (size_t)row0 * N_DIM + n0 + ncol) = v0;
            *reinterpret_cast<__half2*>(g_z + (size_t)(row0 + 8) * N_DIM + n0 + ncol) = v1;
        }
    }
}

// ---------------------------------------------------------------------------
// fused GroupNorm(4) + FiLM + LSTM + GroupNorm(1); z now fp16 (64MB)
// ---------------------------------------------------------------------------
__device__ __forceinline__ float sigmoidf_(float v) {
    return 1.0f / (1.0f + expf(-v));
}

__global__ __launch_bounds__(512) void fused_kernel(
    const float* __restrict__ c, const float* __restrict__ u,
    const float* __restrict__ gamma, const float* __restrict__ beta,
    float* __restrict__ out)
{
    const int row  = blockIdx.x;
    const int t    = threadIdx.x;
    const int warp = t >> 5;
    const int lane = t & 31;

    const __half* zr = g_z + (size_t)row * N_DIM;
    float z[4];
    z[0] = __half2float(zr[t]);
    z[1] = __half2float(zr[t + 512]);
    z[2] = __half2float(zr[t + 1024]);
    z[3] = __half2float(zr[t + 1536]);

    __shared__ float sred[16][8];
    __shared__ float sfin[8];

    float p[8];
#pragma unroll
    for (int q = 0; q < 4; q++) { p[q] = z[q]; p[4 + q] = z[q] * z[q]; }
#pragma unroll
    for (int off = 16; off > 0; off >>= 1)
#pragma unroll
        for (int q = 0; q < 8; q++)
            p[q] += __shfl_down_sync(0xFFFFFFFFu, p[q], off);
    if (lane == 0)
#pragma unroll
        for (int q = 0; q < 8; q++) sred[warp][q] = p[q];
    __syncthreads();
    if (t < 8) {
        float s = 0.0f;
#pragma unroll
        for (int w = 0; w < 16; w++) s += sred[w][t];
        sfin[t] = s;
    }
    __syncthreads();

    float mean[4], rstd[4];
#pragma unroll
    for (int g = 0; g < 4; g++) {
        mean[g] = sfin[g] * (1.0f / 512.0f);
        float var = sfin[4 + g] * (1.0f / 512.0f) - mean[g] * mean[g];
        rstd[g] = rsqrtf(var + EPS);
    }

    const float* ur = u + (size_t)row * (2 * N_DIM);
    float zn[4];
#pragma unroll
    for (int g = 0; g < 4; g++) {
        int idx = g * 512 + t;
        float a  = ur[idx];
        float bb = ur[N_DIM + idx];
        zn[g] = (z[g] - mean[g]) * rstd[g] * (1.0f + a) + bb;
    }

    float cv    = c[(size_t)row * HID + t];
    float c_new = sigmoidf_(zn[1]) * cv + sigmoidf_(zn[0]) * tanhf(zn[3]);

    float s = c_new, ss = c_new * c_new;
#pragma unroll
    for (int off = 16; off > 0; off >>= 1) {
        s  += __shfl_down_sync(0xFFFFFFFFu, s, off);
        ss += __shfl_down_sync(0xFFFFFFFFu, ss, off);
    }
    if (lane == 0) { sred[warp][0] = s; sred[warp][1] = ss; }
    __syncthreads();
    if (t < 2) {
        float acc = 0.0f;
#pragma unroll
        for (int w = 0; w < 16; w++) acc += sred[w][t];
        sfin[t] = acc;
    }
    __syncthreads();

    float m2 = sfin[0] * (1.0f / 512.0f);
    float v2 = sfin[1] * (1.0f / 512.0f) - m2 * m2;
    float cn = (c_new - m2) * rsqrtf(v2 + EPS) * gamma[t] + beta[t];

    float h_new = sigmoidf_(zn[2]) * tanhf(cn);

    out[(size_t)row * HID + t] = h_new;
    out[(size_t)B_SZ * HID + (size_t)row * HID + t] = c_new;
}

// ---------------------------------------------------------------------------
extern "C" void kernel_launch(void* const* d_in, const int* in_sizes, int n_in,
                              void* d_out, int out_size)
{
    const float* x     = (const float*)d_in[0];
    const float* h     = (const float*)d_in[1];
    const float* c     = (const float*)d_in[2];
    const float* u     = (const float*)d_in[3];
    const float* W     = (const float*)d_in[4];
    const float* b_lin = (const float*)d_in[5];
    const float* gamma = (const float*)d_in[6];
    const float* beta  = (const float*)d_in[7];
    float* out = (float*)d_out;

    cudaFuncSetAttribute(gemm_tc_kernel,
                         cudaFuncAttributeMaxDynamicSharedMemorySize, SMEM_TOTAL);

    convA_kernel<<<(B_SZ * K_DIM / 4) / 256, 256>>>(x, h);
    convW_kernel<<<dim3(N_DIM / 32, K_DIM / 32), dim3(32, 32)>>>(W);
    gemm_tc_kernel<<<dim3(N_DIM / 256, B_SZ / 128), 256, SMEM_TOTAL>>>(b_lin);
    fused_kernel<<<B_SZ, 512>>>(c, u, gamma, beta, out);
}